// round 1
// baseline (speedup 1.0000x reference)
#include <cuda_runtime.h>
#include <cuda_bf16.h>
#include <math.h>

// ---------------- problem constants ----------------
#define N_NODES   10000
#define N_EDGES   50000
#define NS_       48
#define NV_       10
#define NEF_      128
#define HID_      128
#define CH_       78          // NS + 3*NV
#define W1N_      2304        // NS*NS
#define W2N_      480         // NS*NV
#define W3N_      100         // NV*NV
#define W4N_      480         // NV*NS
#define WTOT_     3364
#define OFF2_     2304
#define OFF3_     2784
#define OFF4_     2884
#define EPS_      1e-05f
#define INV_SQRT3_ 0.57735026918962576f
#define NORM0_    0.13130643285972254f   // 1/sqrt(58)
#define NORM1_    0.13130643285972254f

#define TE 32      // edges per CTA
#define NC 128     // w-columns per tile
#define NTHREADS 256

// ---------------- device scratch (allocation-free) ----------------
__device__ float g_h[N_EDGES * HID_];          // hidden activations (25.6 MB)
__device__ float g_sum[N_NODES * CH_];         // segment sums
__device__ float g_cnt[N_NODES];               // segment counts
__device__ float g_node[N_NODES * CH_];        // post-residual node features
__device__ float g_stats[NS_ + NS_ + NV_];     // [0,48) sum_s, [48,96) sum_s2, [96,106) sum_v2

// smem sizes
#define SM1_FLOATS (128*36 + 128*128)                       // EaT + W1s
#define SM1_BYTES  (SM1_FLOATS * 4)
#define SM2_FLOATS (128*36 + 128*128 + TE*132 + TE*48 + TE*30 + TE*10 + TE*4 + TE*136)
#define SM2_BYTES  (SM2_FLOATS * 4)

// ---------------- K0: zero scratch ----------------
__global__ void k0_zero() {
    const int total = N_NODES * CH_ + N_NODES + (NS_ + NS_ + NV_);
    for (int i = blockIdx.x * blockDim.x + threadIdx.x; i < total;
         i += gridDim.x * blockDim.x) {
        if (i < N_NODES * CH_)             g_sum[i] = 0.f;
        else if (i < N_NODES * CH_ + N_NODES) g_cnt[i - N_NODES * CH_] = 0.f;
        else g_stats[i - N_NODES * CH_ - N_NODES] = 0.f;
    }
}

// ---------------- K1: h = relu(edge_attr @ fc_w1 + fc_b1) ----------------
__global__ __launch_bounds__(NTHREADS, 1)
void k1_hidden(const float* __restrict__ edge_attr,
               const float* __restrict__ fc_w1,
               const float* __restrict__ fc_b1) {
    extern __shared__ float sm[];
    float* EaT = sm;             // [128][36] transposed edge_attr tile (padded)
    float* W1s = sm + 128 * 36;  // [128][128]

    const int tid = threadIdx.x;
    const int e_base = blockIdx.x * TE;

    // load edge_attr tile transposed: gmem coalesced (consecutive j)
    for (int idx = tid; idx < TE * 128; idx += NTHREADS) {
        int j = idx & 127, e = idx >> 7;
        int ge = e_base + e;
        EaT[j * 36 + e] = (ge < N_EDGES) ? edge_attr[(size_t)ge * 128 + j] : 0.f;
    }
    // load fc_w1 fully (float4)
    for (int idx = tid; idx < 4096; idx += NTHREADS)
        *reinterpret_cast<float4*>(&W1s[idx * 4]) =
            *reinterpret_cast<const float4*>(&fc_w1[idx * 4]);
    __syncthreads();

    const int e0 = (tid & 7) * 4;
    const int c0 = (tid >> 3) * 4;

    float acc[4][4];
#pragma unroll
    for (int b = 0; b < 4; ++b) {
        float bb = __ldg(&fc_b1[c0 + b]);
#pragma unroll
        for (int a = 0; a < 4; ++a) acc[a][b] = bb;
    }

#pragma unroll 4
    for (int j = 0; j < 128; ++j) {
        float4 hv = *reinterpret_cast<const float4*>(&EaT[j * 36 + e0]);
        float4 wv = *reinterpret_cast<const float4*>(&W1s[j * 128 + c0]);
        float h[4] = {hv.x, hv.y, hv.z, hv.w};
        float w[4] = {wv.x, wv.y, wv.z, wv.w};
#pragma unroll
        for (int a = 0; a < 4; ++a)
#pragma unroll
            for (int b = 0; b < 4; ++b)
                acc[a][b] = fmaf(h[a], w[b], acc[a][b]);
    }

#pragma unroll
    for (int a = 0; a < 4; ++a) {
        int ge = e_base + e0 + a;
        if (ge < N_EDGES) {
            float4 o = make_float4(fmaxf(acc[a][0], 0.f), fmaxf(acc[a][1], 0.f),
                                   fmaxf(acc[a][2], 0.f), fmaxf(acc[a][3], 0.f));
            *reinterpret_cast<float4*>(&g_h[(size_t)ge * 128 + c0]) = o;
        }
    }
}

// ---------------- K2: fused w-GEMM + tensor-product contraction + scatter --
__global__ __launch_bounds__(NTHREADS, 1)
void k2_fused(const float* __restrict__ node_attr,
              const int*   __restrict__ edge_index,
              const float* __restrict__ edge_sh,
              const float* __restrict__ fc_w2,
              const float* __restrict__ fc_b2) {
    extern __shared__ float sm[];
    float* HsT  = sm;                     // [128][36]  transposed h tile
    float* W2s  = HsT  + 128 * 36;        // [128][128] fc_w2 tile
    float* Wt   = W2s  + 128 * 128;       // [TE][132]  w tile (GEMM result)
    float* sF   = Wt   + TE * 132;        // [TE][48]   scalar features
    float* vinF = sF   + TE * 48;         // [TE][30]   vector features (u*3+i)
    float* dotF = vinF + TE * 30;         // [TE][10]   dot features
    float* shS  = dotF + TE * 10;         // [TE][4]    spherical harmonics
    float* Acc  = shS  + TE * 4;          // [TE][136]  output accumulators

    const int tid = threadIdx.x;
    const int e_base = blockIdx.x * TE;

    // load h tile transposed (gmem coalesced over j)
    for (int idx = tid; idx < TE * 128; idx += NTHREADS) {
        int j = idx & 127, e = idx >> 7;
        int ge = e_base + e;
        HsT[j * 36 + e] = (ge < N_EDGES) ? g_h[(size_t)ge * 128 + j] : 0.f;
    }
    // gather node features for dst nodes
    for (int idx = tid; idx < TE * CH_; idx += NTHREADS) {
        int e = idx / CH_, k = idx % CH_;
        int ge = e_base + e;
        float val = 0.f;
        if (ge < N_EDGES) {
            int dst = edge_index[N_EDGES + ge];
            val = node_attr[(size_t)dst * CH_ + k];
        }
        if (k < NS_) sF[e * 48 + k] = val;
        else         vinF[e * 30 + (k - NS_)] = val;
    }
    for (int idx = tid; idx < TE * 4; idx += NTHREADS) {
        int e = idx >> 2, q = idx & 3;
        int ge = e_base + e;
        shS[idx] = (ge < N_EDGES) ? edge_sh[(size_t)ge * 4 + q] : 0.f;
    }
    for (int idx = tid; idx < TE * 136; idx += NTHREADS) Acc[idx] = 0.f;
    __syncthreads();
    // dot[e][u] = (v_in[u] . sh1) * INV_SQRT3
    for (int idx = tid; idx < TE * 10; idx += NTHREADS) {
        int e = idx / 10, u = idx % 10;
        const float* vv = &vinF[e * 30 + u * 3];
        dotF[idx] = (vv[0] * shS[e * 4 + 1] + vv[1] * shS[e * 4 + 2] +
                     vv[2] * shS[e * 4 + 3]) * INV_SQRT3_;
    }
    __syncthreads();

    const int e0 = (tid & 7) * 4;
    const int c0 = (tid >> 3) * 4;

    for (int ct = 0; ct < WTOT_; ct += NC) {
        // ---- load fc_w2 tile ----
        if (ct + NC <= WTOT_) {
            for (int idx = tid; idx < 128 * (NC / 4); idx += NTHREADS) {
                int c4 = idx & 31, j = idx >> 5;
                *reinterpret_cast<float4*>(&W2s[j * 128 + c4 * 4]) =
                    *reinterpret_cast<const float4*>(&fc_w2[(size_t)j * WTOT_ + ct + c4 * 4]);
            }
        } else {
            for (int idx = tid; idx < 128 * NC; idx += NTHREADS) {
                int c = idx & 127, j = idx >> 7;
                int gc = ct + c;
                W2s[j * 128 + c] = (gc < WTOT_) ? fc_w2[(size_t)j * WTOT_ + gc] : 0.f;
            }
        }
        __syncthreads();

        // ---- GEMM: Wt[e][c] = h[e] . fc_w2[:, ct+c] + b2 ----
        float acc[4][4];
#pragma unroll
        for (int b = 0; b < 4; ++b) {
            int gc = ct + c0 + b;
            float bb = (gc < WTOT_) ? __ldg(&fc_b2[gc]) : 0.f;
#pragma unroll
            for (int a = 0; a < 4; ++a) acc[a][b] = bb;
        }
#pragma unroll 4
        for (int j = 0; j < 128; ++j) {
            float4 hv = *reinterpret_cast<const float4*>(&HsT[j * 36 + e0]);
            float4 wv = *reinterpret_cast<const float4*>(&W2s[j * 128 + c0]);
            float h[4] = {hv.x, hv.y, hv.z, hv.w};
            float w[4] = {wv.x, wv.y, wv.z, wv.w};
#pragma unroll
            for (int a = 0; a < 4; ++a)
#pragma unroll
                for (int b = 0; b < 4; ++b)
                    acc[a][b] = fmaf(h[a], w[b], acc[a][b]);
        }
#pragma unroll
        for (int a = 0; a < 4; ++a) {
            float4 o = make_float4(acc[a][0], acc[a][1], acc[a][2], acc[a][3]);
            *reinterpret_cast<float4*>(&Wt[(e0 + a) * 132 + c0]) = o;
        }
        __syncthreads();

        // ---- contraction: owner-computes, no atomics ----
        // 116 slots/edge: [0,48) out0a, [48,96) out0b, [96,106) out1a, [106,116) out1b(v: 3 comps)
        const int cend = ct + NC;
        for (int s = tid; s < TE * 116; s += NTHREADS) {
            int e = s / 116, r = s % 116;
            float* Ae = &Acc[e * 136];
            const float* We = &Wt[e * 132];
            if (r < 48) {                 // w1: c = u*48+v, feat s[u] -> out0a[v]
                int v = r;
                int u = (ct > v) ? (ct - v + 47) / 48 : 0;
                int c = u * 48 + v;
                float a = Ae[v];
                const float* se = &sF[e * 48];
                while (u < 48 && c < cend) { a += se[u] * We[c - ct]; ++u; c += 48; }
                Ae[v] = a;
            } else if (r < 96) {          // w4: c = 2884+u*48+v, feat dot[u] -> out0b[v]
                int v = r - 48;
                int rel = ct - OFF4_;
                int u = (rel > v) ? (rel - v + 47) / 48 : 0;
                int c = OFF4_ + u * 48 + v;
                float a = Ae[48 + v];
                const float* de = &dotF[e * 10];
                while (u < 10 && c < cend) { a += de[u] * We[c - ct]; ++u; c += 48; }
                Ae[48 + v] = a;
            } else if (r < 106) {         // w2: c = 2304+u*10+v, feat s[u] -> out1a[v]
                int v = r - 96;
                int rel = ct - OFF2_;
                int u = (rel > v) ? (rel - v + 9) / 10 : 0;
                int c = OFF2_ + u * 10 + v;
                float a = Ae[96 + v];
                const float* se = &sF[e * 48];
                while (u < 48 && c < cend) { a += se[u] * We[c - ct]; ++u; c += 10; }
                Ae[96 + v] = a;
            } else {                      // w3: c = 2784+u*10+v, feat vin[u][i] -> out1b[v][i]
                int v = r - 106;
                int rel = ct - OFF3_;
                int u = (rel > v) ? (rel - v + 9) / 10 : 0;
                int c = OFF3_ + u * 10 + v;
                float a0 = Ae[106 + v * 3 + 0];
                float a1 = Ae[106 + v * 3 + 1];
                float a2 = Ae[106 + v * 3 + 2];
                const float* ve = &vinF[e * 30];
                while (u < 10 && c < cend) {
                    float wv = We[c - ct];
                    a0 += ve[u * 3 + 0] * wv;
                    a1 += ve[u * 3 + 1] * wv;
                    a2 += ve[u * 3 + 2] * wv;
                    ++u; c += 10;
                }
                Ae[106 + v * 3 + 0] = a0;
                Ae[106 + v * 3 + 1] = a1;
                Ae[106 + v * 3 + 2] = a2;
            }
        }
        __syncthreads();
    }

    // ---- epilogue: combine with sh, scatter-add to src nodes ----
    for (int idx = tid; idx < TE * CH_; idx += NTHREADS) {
        int e = idx / CH_, k = idx % CH_;
        int ge = e_base + e;
        if (ge >= N_EDGES) continue;
        float sh0 = shS[e * 4];
        float val;
        if (k < NS_) {
            val = (Acc[e * 136 + k] * sh0 + Acc[e * 136 + 48 + k]) * NORM0_;
        } else {
            int kk = k - NS_;
            int v = kk / 3, i = kk % 3;
            val = (Acc[e * 136 + 96 + v] * shS[e * 4 + 1 + i] +
                   Acc[e * 136 + 106 + kk] * sh0) * NORM1_;
        }
        int src = edge_index[ge];
        atomicAdd(&g_sum[(size_t)src * CH_ + k], val);
        if (k == 0) atomicAdd(&g_cnt[src], 1.f);
    }
}

// ---------------- K3: node average + residual + stat sums ----------------
__device__ __forceinline__ float block_sum256(float v, float* red) {
#pragma unroll
    for (int off = 16; off > 0; off >>= 1)
        v += __shfl_down_sync(0xffffffffu, v, off);
    int w = threadIdx.x >> 5;
    if ((threadIdx.x & 31) == 0) red[w] = v;
    __syncthreads();
    float r = 0.f;
    if (threadIdx.x < 8) {
        r = red[threadIdx.x];
#pragma unroll
        for (int off = 4; off > 0; off >>= 1)
            r += __shfl_down_sync(0xffu, r, off);
    }
    __syncthreads();
    return r;  // valid in thread 0
}

__global__ void k3_combine(const float* __restrict__ node_attr) {
    __shared__ float red[8];
    int n = blockIdx.x * 256 + threadIdx.x;
    bool valid = n < N_NODES;
    float inv = 1.f;
    if (valid) inv = 1.f / fmaxf(g_cnt[n], 1.f);
    for (int k = 0; k < CH_; ++k) {
        float o = 0.f;
        if (valid) {
            o = g_sum[(size_t)n * CH_ + k] * inv + node_attr[(size_t)n * CH_ + k];
            g_node[(size_t)n * CH_ + k] = o;
        }
        if (k < NS_) {
            float s1 = block_sum256(o, red);
            if (threadIdx.x == 0) atomicAdd(&g_stats[k], s1);
            float s2 = block_sum256(o * o, red);
            if (threadIdx.x == 0) atomicAdd(&g_stats[48 + k], s2);
        } else {
            float s2 = block_sum256(o * o, red);
            if (threadIdx.x == 0) atomicAdd(&g_stats[96 + (k - NS_) / 3], s2);
        }
    }
}

// ---------------- K4: batch norm + write output ----------------
__global__ void k4_final(const float* __restrict__ bn_w,
                         const float* __restrict__ bn_b,
                         float* __restrict__ out) {
    int idx = blockIdx.x * 256 + threadIdx.x;
    if (idx >= N_NODES * CH_) return;
    int k = idx % CH_;
    float o = g_node[idx];
    float res;
    if (k < NS_) {
        float mean = g_stats[k] * (1.f / N_NODES);
        float var  = g_stats[48 + k] * (1.f / N_NODES) - mean * mean;
        res = (o - mean) * rsqrtf(var + EPS_) * __ldg(&bn_w[k]) + __ldg(&bn_b[k]);
    } else {
        int v = (k - NS_) / 3;
        float vn = g_stats[96 + v] * (1.f / (3.f * N_NODES));
        res = o * rsqrtf(vn + EPS_) * __ldg(&bn_w[NS_ + v]);
    }
    out[idx] = res;
}

// ---------------- launch ----------------
extern "C" void kernel_launch(void* const* d_in, const int* in_sizes, int n_in,
                              void* d_out, int out_size) {
    const float* node_attr  = (const float*)d_in[0];
    const int*   edge_index = (const int*)  d_in[1];
    const float* edge_attr  = (const float*)d_in[2];
    const float* edge_sh    = (const float*)d_in[3];
    const float* fc_w1      = (const float*)d_in[4];
    const float* fc_b1      = (const float*)d_in[5];
    const float* fc_w2      = (const float*)d_in[6];
    const float* fc_b2      = (const float*)d_in[7];
    const float* bn_w       = (const float*)d_in[8];
    const float* bn_b       = (const float*)d_in[9];
    float* out = (float*)d_out;

    cudaFuncSetAttribute(k1_hidden, cudaFuncAttributeMaxDynamicSharedMemorySize, SM1_BYTES);
    cudaFuncSetAttribute(k2_fused,  cudaFuncAttributeMaxDynamicSharedMemorySize, SM2_BYTES);

    const int gridE = (N_EDGES + TE - 1) / TE;

    k0_zero<<<512, 256>>>();
    k1_hidden<<<gridE, NTHREADS, SM1_BYTES>>>(edge_attr, fc_w1, fc_b1);
    k2_fused<<<gridE, NTHREADS, SM2_BYTES>>>(node_attr, edge_index, edge_sh, fc_w2, fc_b2);
    k3_combine<<<(N_NODES + 255) / 256, 256>>>(node_attr);
    k4_final<<<(N_NODES * CH_ + 255) / 256, 256>>>(bn_w, bn_b, out);
}

// round 2
// speedup vs baseline: 1.0002x; 1.0002x over previous
#include <cuda_runtime.h>
#include <cuda_bf16.h>
#include <math.h>

// ---------------- problem constants ----------------
#define N_NODES   10000
#define N_EDGES   50000
#define NS_       48
#define NV_       10
#define NEF_      128
#define HID_      128
#define CH_       78          // NS + 3*NV
#define W1N_      2304        // NS*NS
#define W2N_      480         // NS*NV
#define W3N_      100         // NV*NV
#define W4N_      480         // NV*NS
#define WTOT_     3364
#define OFF2_     2304
#define OFF3_     2784
#define OFF4_     2884
#define EPS_      1e-05f
#define INV_SQRT3_ 0.57735026918962576f
#define NORM0_    0.13130643285972254f   // 1/sqrt(58)
#define NORM1_    0.13130643285972254f

#define TE 32      // edges per CTA
#define NC 128     // w-columns per tile
#define NTHREADS 256

// ---------------- device scratch (allocation-free) ----------------
__device__ float g_h[N_EDGES * HID_];          // hidden activations (25.6 MB)
__device__ float g_sum[N_NODES * CH_];         // segment sums
__device__ float g_cnt[N_NODES];               // segment counts
__device__ float g_node[N_NODES * CH_];        // post-residual node features
__device__ float g_stats[NS_ + NS_ + NV_];     // [0,48) sum_s, [48,96) sum_s2, [96,106) sum_v2

// smem sizes
#define SM1_FLOATS (128*36 + 128*128)                       // EaT + W1s
#define SM1_BYTES  (SM1_FLOATS * 4)
#define SM2_FLOATS (128*36 + 128*128 + TE*132 + TE*48 + TE*30 + TE*10 + TE*4 + TE*136)
#define SM2_BYTES  (SM2_FLOATS * 4)

// ---------------- K0: zero scratch ----------------
__global__ void k0_zero() {
    const int total = N_NODES * CH_ + N_NODES + (NS_ + NS_ + NV_);
    for (int i = blockIdx.x * blockDim.x + threadIdx.x; i < total;
         i += gridDim.x * blockDim.x) {
        if (i < N_NODES * CH_)             g_sum[i] = 0.f;
        else if (i < N_NODES * CH_ + N_NODES) g_cnt[i - N_NODES * CH_] = 0.f;
        else g_stats[i - N_NODES * CH_ - N_NODES] = 0.f;
    }
}

// ---------------- K1: h = relu(edge_attr @ fc_w1 + fc_b1) ----------------
__global__ __launch_bounds__(NTHREADS, 1)
void k1_hidden(const float* __restrict__ edge_attr,
               const float* __restrict__ fc_w1,
               const float* __restrict__ fc_b1) {
    extern __shared__ float sm[];
    float* EaT = sm;             // [128][36] transposed edge_attr tile (padded)
    float* W1s = sm + 128 * 36;  // [128][128]

    const int tid = threadIdx.x;
    const int e_base = blockIdx.x * TE;

    // load edge_attr tile transposed: gmem coalesced (consecutive j)
    for (int idx = tid; idx < TE * 128; idx += NTHREADS) {
        int j = idx & 127, e = idx >> 7;
        int ge = e_base + e;
        EaT[j * 36 + e] = (ge < N_EDGES) ? edge_attr[(size_t)ge * 128 + j] : 0.f;
    }
    // load fc_w1 fully (float4)
    for (int idx = tid; idx < 4096; idx += NTHREADS)
        *reinterpret_cast<float4*>(&W1s[idx * 4]) =
            *reinterpret_cast<const float4*>(&fc_w1[idx * 4]);
    __syncthreads();

    const int e0 = (tid & 7) * 4;
    const int c0 = (tid >> 3) * 4;

    float acc[4][4];
#pragma unroll
    for (int b = 0; b < 4; ++b) {
        float bb = __ldg(&fc_b1[c0 + b]);
#pragma unroll
        for (int a = 0; a < 4; ++a) acc[a][b] = bb;
    }

#pragma unroll 4
    for (int j = 0; j < 128; ++j) {
        float4 hv = *reinterpret_cast<const float4*>(&EaT[j * 36 + e0]);
        float4 wv = *reinterpret_cast<const float4*>(&W1s[j * 128 + c0]);
        float h[4] = {hv.x, hv.y, hv.z, hv.w};
        float w[4] = {wv.x, wv.y, wv.z, wv.w};
#pragma unroll
        for (int a = 0; a < 4; ++a)
#pragma unroll
            for (int b = 0; b < 4; ++b)
                acc[a][b] = fmaf(h[a], w[b], acc[a][b]);
    }

#pragma unroll
    for (int a = 0; a < 4; ++a) {
        int ge = e_base + e0 + a;
        if (ge < N_EDGES) {
            float4 o = make_float4(fmaxf(acc[a][0], 0.f), fmaxf(acc[a][1], 0.f),
                                   fmaxf(acc[a][2], 0.f), fmaxf(acc[a][3], 0.f));
            *reinterpret_cast<float4*>(&g_h[(size_t)ge * 128 + c0]) = o;
        }
    }
}

// ---------------- K2: fused w-GEMM + tensor-product contraction + scatter --
__global__ __launch_bounds__(NTHREADS, 1)
void k2_fused(const float* __restrict__ node_attr,
              const int*   __restrict__ edge_index,
              const float* __restrict__ edge_sh,
              const float* __restrict__ fc_w2,
              const float* __restrict__ fc_b2) {
    extern __shared__ float sm[];
    float* HsT  = sm;                     // [128][36]  transposed h tile
    float* W2s  = HsT  + 128 * 36;        // [128][128] fc_w2 tile
    float* Wt   = W2s  + 128 * 128;       // [TE][132]  w tile (GEMM result)
    float* sF   = Wt   + TE * 132;        // [TE][48]   scalar features
    float* vinF = sF   + TE * 48;         // [TE][30]   vector features (u*3+i)
    float* dotF = vinF + TE * 30;         // [TE][10]   dot features
    float* shS  = dotF + TE * 10;         // [TE][4]    spherical harmonics
    float* Acc  = shS  + TE * 4;          // [TE][136]  output accumulators

    const int tid = threadIdx.x;
    const int e_base = blockIdx.x * TE;

    // load h tile transposed (gmem coalesced over j)
    for (int idx = tid; idx < TE * 128; idx += NTHREADS) {
        int j = idx & 127, e = idx >> 7;
        int ge = e_base + e;
        HsT[j * 36 + e] = (ge < N_EDGES) ? g_h[(size_t)ge * 128 + j] : 0.f;
    }
    // gather node features for dst nodes
    for (int idx = tid; idx < TE * CH_; idx += NTHREADS) {
        int e = idx / CH_, k = idx % CH_;
        int ge = e_base + e;
        float val = 0.f;
        if (ge < N_EDGES) {
            int dst = edge_index[N_EDGES + ge];
            val = node_attr[(size_t)dst * CH_ + k];
        }
        if (k < NS_) sF[e * 48 + k] = val;
        else         vinF[e * 30 + (k - NS_)] = val;
    }
    for (int idx = tid; idx < TE * 4; idx += NTHREADS) {
        int e = idx >> 2, q = idx & 3;
        int ge = e_base + e;
        shS[idx] = (ge < N_EDGES) ? edge_sh[(size_t)ge * 4 + q] : 0.f;
    }
    for (int idx = tid; idx < TE * 136; idx += NTHREADS) Acc[idx] = 0.f;
    __syncthreads();
    // dot[e][u] = (v_in[u] . sh1) * INV_SQRT3
    for (int idx = tid; idx < TE * 10; idx += NTHREADS) {
        int e = idx / 10, u = idx % 10;
        const float* vv = &vinF[e * 30 + u * 3];
        dotF[idx] = (vv[0] * shS[e * 4 + 1] + vv[1] * shS[e * 4 + 2] +
                     vv[2] * shS[e * 4 + 3]) * INV_SQRT3_;
    }
    __syncthreads();

    const int e0 = (tid & 7) * 4;
    const int c0 = (tid >> 3) * 4;

    for (int ct = 0; ct < WTOT_; ct += NC) {
        // ---- load fc_w2 tile ----
        if (ct + NC <= WTOT_) {
            for (int idx = tid; idx < 128 * (NC / 4); idx += NTHREADS) {
                int c4 = idx & 31, j = idx >> 5;
                *reinterpret_cast<float4*>(&W2s[j * 128 + c4 * 4]) =
                    *reinterpret_cast<const float4*>(&fc_w2[(size_t)j * WTOT_ + ct + c4 * 4]);
            }
        } else {
            for (int idx = tid; idx < 128 * NC; idx += NTHREADS) {
                int c = idx & 127, j = idx >> 7;
                int gc = ct + c;
                W2s[j * 128 + c] = (gc < WTOT_) ? fc_w2[(size_t)j * WTOT_ + gc] : 0.f;
            }
        }
        __syncthreads();

        // ---- GEMM: Wt[e][c] = h[e] . fc_w2[:, ct+c] + b2 ----
        float acc[4][4];
#pragma unroll
        for (int b = 0; b < 4; ++b) {
            int gc = ct + c0 + b;
            float bb = (gc < WTOT_) ? __ldg(&fc_b2[gc]) : 0.f;
#pragma unroll
            for (int a = 0; a < 4; ++a) acc[a][b] = bb;
        }
#pragma unroll 4
        for (int j = 0; j < 128; ++j) {
            float4 hv = *reinterpret_cast<const float4*>(&HsT[j * 36 + e0]);
            float4 wv = *reinterpret_cast<const float4*>(&W2s[j * 128 + c0]);
            float h[4] = {hv.x, hv.y, hv.z, hv.w};
            float w[4] = {wv.x, wv.y, wv.z, wv.w};
#pragma unroll
            for (int a = 0; a < 4; ++a)
#pragma unroll
                for (int b = 0; b < 4; ++b)
                    acc[a][b] = fmaf(h[a], w[b], acc[a][b]);
        }
#pragma unroll
        for (int a = 0; a < 4; ++a) {
            float4 o = make_float4(acc[a][0], acc[a][1], acc[a][2], acc[a][3]);
            *reinterpret_cast<float4*>(&Wt[(e0 + a) * 132 + c0]) = o;
        }
        __syncthreads();

        // ---- contraction: owner-computes, no atomics ----
        // 116 slots/edge: [0,48) out0a, [48,96) out0b, [96,106) out1a, [106,116) out1b(v: 3 comps)
        const int cend = ct + NC;
        for (int s = tid; s < TE * 116; s += NTHREADS) {
            int e = s / 116, r = s % 116;
            float* Ae = &Acc[e * 136];
            const float* We = &Wt[e * 132];
            if (r < 48) {                 // w1: c = u*48+v, feat s[u] -> out0a[v]
                int v = r;
                int u = (ct > v) ? (ct - v + 47) / 48 : 0;
                int c = u * 48 + v;
                float a = Ae[v];
                const float* se = &sF[e * 48];
                while (u < 48 && c < cend) { a += se[u] * We[c - ct]; ++u; c += 48; }
                Ae[v] = a;
            } else if (r < 96) {          // w4: c = 2884+u*48+v, feat dot[u] -> out0b[v]
                int v = r - 48;
                int rel = ct - OFF4_;
                int u = (rel > v) ? (rel - v + 47) / 48 : 0;
                int c = OFF4_ + u * 48 + v;
                float a = Ae[48 + v];
                const float* de = &dotF[e * 10];
                while (u < 10 && c < cend) { a += de[u] * We[c - ct]; ++u; c += 48; }
                Ae[48 + v] = a;
            } else if (r < 106) {         // w2: c = 2304+u*10+v, feat s[u] -> out1a[v]
                int v = r - 96;
                int rel = ct - OFF2_;
                int u = (rel > v) ? (rel - v + 9) / 10 : 0;
                int c = OFF2_ + u * 10 + v;
                float a = Ae[96 + v];
                const float* se = &sF[e * 48];
                while (u < 48 && c < cend) { a += se[u] * We[c - ct]; ++u; c += 10; }
                Ae[96 + v] = a;
            } else {                      // w3: c = 2784+u*10+v, feat vin[u][i] -> out1b[v][i]
                int v = r - 106;
                int rel = ct - OFF3_;
                int u = (rel > v) ? (rel - v + 9) / 10 : 0;
                int c = OFF3_ + u * 10 + v;
                float a0 = Ae[106 + v * 3 + 0];
                float a1 = Ae[106 + v * 3 + 1];
                float a2 = Ae[106 + v * 3 + 2];
                const float* ve = &vinF[e * 30];
                while (u < 10 && c < cend) {
                    float wv = We[c - ct];
                    a0 += ve[u * 3 + 0] * wv;
                    a1 += ve[u * 3 + 1] * wv;
                    a2 += ve[u * 3 + 2] * wv;
                    ++u; c += 10;
                }
                Ae[106 + v * 3 + 0] = a0;
                Ae[106 + v * 3 + 1] = a1;
                Ae[106 + v * 3 + 2] = a2;
            }
        }
        __syncthreads();
    }

    // ---- epilogue: combine with sh, scatter-add to src nodes ----
    for (int idx = tid; idx < TE * CH_; idx += NTHREADS) {
        int e = idx / CH_, k = idx % CH_;
        int ge = e_base + e;
        if (ge >= N_EDGES) continue;
        float sh0 = shS[e * 4];
        float val;
        if (k < NS_) {
            val = (Acc[e * 136 + k] * sh0 + Acc[e * 136 + 48 + k]) * NORM0_;
        } else {
            int kk = k - NS_;
            int v = kk / 3, i = kk % 3;
            val = (Acc[e * 136 + 96 + v] * shS[e * 4 + 1 + i] +
                   Acc[e * 136 + 106 + kk] * sh0) * NORM1_;
        }
        int src = edge_index[ge];
        atomicAdd(&g_sum[(size_t)src * CH_ + k], val);
        if (k == 0) atomicAdd(&g_cnt[src], 1.f);
    }
}

// ---------------- K3: node average + residual + stat sums ----------------
__device__ __forceinline__ float block_sum256(float v, float* red) {
#pragma unroll
    for (int off = 16; off > 0; off >>= 1)
        v += __shfl_down_sync(0xffffffffu, v, off);
    int w = threadIdx.x >> 5;
    if ((threadIdx.x & 31) == 0) red[w] = v;
    __syncthreads();
    float r = 0.f;
    if (threadIdx.x < 8) {
        r = red[threadIdx.x];
#pragma unroll
        for (int off = 4; off > 0; off >>= 1)
            r += __shfl_down_sync(0xffu, r, off);
    }
    __syncthreads();
    return r;  // valid in thread 0
}

__global__ void k3_combine(const float* __restrict__ node_attr) {
    __shared__ float red[8];
    int n = blockIdx.x * 256 + threadIdx.x;
    bool valid = n < N_NODES;
    float inv = 1.f;
    if (valid) inv = 1.f / fmaxf(g_cnt[n], 1.f);
    for (int k = 0; k < CH_; ++k) {
        float o = 0.f;
        if (valid) {
            o = g_sum[(size_t)n * CH_ + k] * inv + node_attr[(size_t)n * CH_ + k];
            g_node[(size_t)n * CH_ + k] = o;
        }
        if (k < NS_) {
            float s1 = block_sum256(o, red);
            if (threadIdx.x == 0) atomicAdd(&g_stats[k], s1);
            float s2 = block_sum256(o * o, red);
            if (threadIdx.x == 0) atomicAdd(&g_stats[48 + k], s2);
        } else {
            float s2 = block_sum256(o * o, red);
            if (threadIdx.x == 0) atomicAdd(&g_stats[96 + (k - NS_) / 3], s2);
        }
    }
}

// ---------------- K4: batch norm + write output ----------------
__global__ void k4_final(const float* __restrict__ bn_w,
                         const float* __restrict__ bn_b,
                         float* __restrict__ out) {
    int idx = blockIdx.x * 256 + threadIdx.x;
    if (idx >= N_NODES * CH_) return;
    int k = idx % CH_;
    float o = g_node[idx];
    float res;
    if (k < NS_) {
        float mean = g_stats[k] * (1.f / N_NODES);
        float var  = g_stats[48 + k] * (1.f / N_NODES) - mean * mean;
        res = (o - mean) * rsqrtf(var + EPS_) * __ldg(&bn_w[k]) + __ldg(&bn_b[k]);
    } else {
        int v = (k - NS_) / 3;
        float vn = g_stats[96 + v] * (1.f / (3.f * N_NODES));
        res = o * rsqrtf(vn + EPS_) * __ldg(&bn_w[NS_ + v]);
    }
    out[idx] = res;
}

// ---------------- launch ----------------
extern "C" void kernel_launch(void* const* d_in, const int* in_sizes, int n_in,
                              void* d_out, int out_size) {
    const float* node_attr  = (const float*)d_in[0];
    const int*   edge_index = (const int*)  d_in[1];
    const float* edge_attr  = (const float*)d_in[2];
    const float* edge_sh    = (const float*)d_in[3];
    const float* fc_w1      = (const float*)d_in[4];
    const float* fc_b1      = (const float*)d_in[5];
    const float* fc_w2      = (const float*)d_in[6];
    const float* fc_b2      = (const float*)d_in[7];
    const float* bn_w       = (const float*)d_in[8];
    const float* bn_b       = (const float*)d_in[9];
    float* out = (float*)d_out;

    cudaFuncSetAttribute(k1_hidden, cudaFuncAttributeMaxDynamicSharedMemorySize, SM1_BYTES);
    cudaFuncSetAttribute(k2_fused,  cudaFuncAttributeMaxDynamicSharedMemorySize, SM2_BYTES);

    const int gridE = (N_EDGES + TE - 1) / TE;

    k0_zero<<<512, 256>>>();
    k1_hidden<<<gridE, NTHREADS, SM1_BYTES>>>(edge_attr, fc_w1, fc_b1);
    k2_fused<<<gridE, NTHREADS, SM2_BYTES>>>(node_attr, edge_index, edge_sh, fc_w2, fc_b2);
    k3_combine<<<(N_NODES + 255) / 256, 256>>>(node_attr);
    k4_final<<<(N_NODES * CH_ + 255) / 256, 256>>>(bn_w, bn_b, out);
}

// round 3
// speedup vs baseline: 1.0022x; 1.0020x over previous
#include <cuda_runtime.h>
#include <cuda_bf16.h>
#include <math.h>

// ---------------- problem constants ----------------
#define N_NODES   10000
#define N_EDGES   50000
#define NS_       48
#define NV_       10
#define NEF_      128
#define HID_      128
#define CH_       78          // NS + 3*NV
#define W1N_      2304        // NS*NS
#define W2N_      480         // NS*NV
#define W3N_      100         // NV*NV
#define W4N_      480         // NV*NS
#define WTOT_     3364
#define OFF2_     2304
#define OFF3_     2784
#define OFF4_     2884
#define EPS_      1e-05f
#define INV_SQRT3_ 0.57735026918962576f
#define NORM0_    0.13130643285972254f   // 1/sqrt(58)
#define NORM1_    0.13130643285972254f

#define TE 32      // edges per CTA
#define NC 128     // w-columns per tile
#define NTHREADS 256

// ---------------- device scratch (allocation-free) ----------------
__device__ float g_h[N_EDGES * HID_];          // hidden activations (25.6 MB)
__device__ float g_sum[N_NODES * CH_];         // segment sums
__device__ float g_cnt[N_NODES];               // segment counts
__device__ float g_node[N_NODES * CH_];        // post-residual node features
__device__ float g_stats[NS_ + NS_ + NV_];     // [0,48) sum_s, [48,96) sum_s2, [96,106) sum_v2

// smem sizes
#define SM1_FLOATS (128*36 + 128*128)                       // EaT + W1s
#define SM1_BYTES  (SM1_FLOATS * 4)
#define SM2_FLOATS (128*36 + 128*128 + TE*132 + TE*48 + TE*30 + TE*10 + TE*4 + TE*136)
#define SM2_BYTES  (SM2_FLOATS * 4)

// ---------------- K0: zero scratch ----------------
__global__ void k0_zero() {
    const int total = N_NODES * CH_ + N_NODES + (NS_ + NS_ + NV_);
    for (int i = blockIdx.x * blockDim.x + threadIdx.x; i < total;
         i += gridDim.x * blockDim.x) {
        if (i < N_NODES * CH_)             g_sum[i] = 0.f;
        else if (i < N_NODES * CH_ + N_NODES) g_cnt[i - N_NODES * CH_] = 0.f;
        else g_stats[i - N_NODES * CH_ - N_NODES] = 0.f;
    }
}

// ---------------- K1: h = relu(edge_attr @ fc_w1 + fc_b1) ----------------
__global__ __launch_bounds__(NTHREADS, 1)
void k1_hidden(const float* __restrict__ edge_attr,
               const float* __restrict__ fc_w1,
               const float* __restrict__ fc_b1) {
    extern __shared__ float sm[];
    float* EaT = sm;             // [128][36] transposed edge_attr tile (padded)
    float* W1s = sm + 128 * 36;  // [128][128]

    const int tid = threadIdx.x;
    const int e_base = blockIdx.x * TE;

    // load edge_attr tile transposed: gmem coalesced (consecutive j)
    for (int idx = tid; idx < TE * 128; idx += NTHREADS) {
        int j = idx & 127, e = idx >> 7;
        int ge = e_base + e;
        EaT[j * 36 + e] = (ge < N_EDGES) ? edge_attr[(size_t)ge * 128 + j] : 0.f;
    }
    // load fc_w1 fully (float4)
    for (int idx = tid; idx < 4096; idx += NTHREADS)
        *reinterpret_cast<float4*>(&W1s[idx * 4]) =
            *reinterpret_cast<const float4*>(&fc_w1[idx * 4]);
    __syncthreads();

    const int e0 = (tid & 7) * 4;
    const int c0 = (tid >> 3) * 4;

    float acc[4][4];
#pragma unroll
    for (int b = 0; b < 4; ++b) {
        float bb = __ldg(&fc_b1[c0 + b]);
#pragma unroll
        for (int a = 0; a < 4; ++a) acc[a][b] = bb;
    }

#pragma unroll 4
    for (int j = 0; j < 128; ++j) {
        float4 hv = *reinterpret_cast<const float4*>(&EaT[j * 36 + e0]);
        float4 wv = *reinterpret_cast<const float4*>(&W1s[j * 128 + c0]);
        float h[4] = {hv.x, hv.y, hv.z, hv.w};
        float w[4] = {wv.x, wv.y, wv.z, wv.w};
#pragma unroll
        for (int a = 0; a < 4; ++a)
#pragma unroll
            for (int b = 0; b < 4; ++b)
                acc[a][b] = fmaf(h[a], w[b], acc[a][b]);
    }

#pragma unroll
    for (int a = 0; a < 4; ++a) {
        int ge = e_base + e0 + a;
        if (ge < N_EDGES) {
            float4 o = make_float4(fmaxf(acc[a][0], 0.f), fmaxf(acc[a][1], 0.f),
                                   fmaxf(acc[a][2], 0.f), fmaxf(acc[a][3], 0.f));
            *reinterpret_cast<float4*>(&g_h[(size_t)ge * 128 + c0]) = o;
        }
    }
}

// ---------------- K2: fused w-GEMM + tensor-product contraction + scatter --
__global__ __launch_bounds__(NTHREADS, 1)
void k2_fused(const float* __restrict__ node_attr,
              const int*   __restrict__ edge_index,
              const float* __restrict__ edge_sh,
              const float* __restrict__ fc_w2,
              const float* __restrict__ fc_b2) {
    extern __shared__ float sm[];
    float* HsT  = sm;                     // [128][36]  transposed h tile
    float* W2s  = HsT  + 128 * 36;        // [128][128] fc_w2 tile
    float* Wt   = W2s  + 128 * 128;       // [TE][132]  w tile (GEMM result)
    float* sF   = Wt   + TE * 132;        // [TE][48]   scalar features
    float* vinF = sF   + TE * 48;         // [TE][30]   vector features (u*3+i)
    float* dotF = vinF + TE * 30;         // [TE][10]   dot features
    float* shS  = dotF + TE * 10;         // [TE][4]    spherical harmonics
    float* Acc  = shS  + TE * 4;          // [TE][136]  output accumulators

    const int tid = threadIdx.x;
    const int e_base = blockIdx.x * TE;

    // load h tile transposed (gmem coalesced over j)
    for (int idx = tid; idx < TE * 128; idx += NTHREADS) {
        int j = idx & 127, e = idx >> 7;
        int ge = e_base + e;
        HsT[j * 36 + e] = (ge < N_EDGES) ? g_h[(size_t)ge * 128 + j] : 0.f;
    }
    // gather node features for dst nodes
    for (int idx = tid; idx < TE * CH_; idx += NTHREADS) {
        int e = idx / CH_, k = idx % CH_;
        int ge = e_base + e;
        float val = 0.f;
        if (ge < N_EDGES) {
            int dst = edge_index[N_EDGES + ge];
            val = node_attr[(size_t)dst * CH_ + k];
        }
        if (k < NS_) sF[e * 48 + k] = val;
        else         vinF[e * 30 + (k - NS_)] = val;
    }
    for (int idx = tid; idx < TE * 4; idx += NTHREADS) {
        int e = idx >> 2, q = idx & 3;
        int ge = e_base + e;
        shS[idx] = (ge < N_EDGES) ? edge_sh[(size_t)ge * 4 + q] : 0.f;
    }
    for (int idx = tid; idx < TE * 136; idx += NTHREADS) Acc[idx] = 0.f;
    __syncthreads();
    // dot[e][u] = (v_in[u] . sh1) * INV_SQRT3
    for (int idx = tid; idx < TE * 10; idx += NTHREADS) {
        int e = idx / 10, u = idx % 10;
        const float* vv = &vinF[e * 30 + u * 3];
        dotF[idx] = (vv[0] * shS[e * 4 + 1] + vv[1] * shS[e * 4 + 2] +
                     vv[2] * shS[e * 4 + 3]) * INV_SQRT3_;
    }
    __syncthreads();

    const int e0 = (tid & 7) * 4;
    const int c0 = (tid >> 3) * 4;

    for (int ct = 0; ct < WTOT_; ct += NC) {
        // ---- load fc_w2 tile ----
        if (ct + NC <= WTOT_) {
            for (int idx = tid; idx < 128 * (NC / 4); idx += NTHREADS) {
                int c4 = idx & 31, j = idx >> 5;
                *reinterpret_cast<float4*>(&W2s[j * 128 + c4 * 4]) =
                    *reinterpret_cast<const float4*>(&fc_w2[(size_t)j * WTOT_ + ct + c4 * 4]);
            }
        } else {
            for (int idx = tid; idx < 128 * NC; idx += NTHREADS) {
                int c = idx & 127, j = idx >> 7;
                int gc = ct + c;
                W2s[j * 128 + c] = (gc < WTOT_) ? fc_w2[(size_t)j * WTOT_ + gc] : 0.f;
            }
        }
        __syncthreads();

        // ---- GEMM: Wt[e][c] = h[e] . fc_w2[:, ct+c] + b2 ----
        float acc[4][4];
#pragma unroll
        for (int b = 0; b < 4; ++b) {
            int gc = ct + c0 + b;
            float bb = (gc < WTOT_) ? __ldg(&fc_b2[gc]) : 0.f;
#pragma unroll
            for (int a = 0; a < 4; ++a) acc[a][b] = bb;
        }
#pragma unroll 4
        for (int j = 0; j < 128; ++j) {
            float4 hv = *reinterpret_cast<const float4*>(&HsT[j * 36 + e0]);
            float4 wv = *reinterpret_cast<const float4*>(&W2s[j * 128 + c0]);
            float h[4] = {hv.x, hv.y, hv.z, hv.w};
            float w[4] = {wv.x, wv.y, wv.z, wv.w};
#pragma unroll
            for (int a = 0; a < 4; ++a)
#pragma unroll
                for (int b = 0; b < 4; ++b)
                    acc[a][b] = fmaf(h[a], w[b], acc[a][b]);
        }
#pragma unroll
        for (int a = 0; a < 4; ++a) {
            float4 o = make_float4(acc[a][0], acc[a][1], acc[a][2], acc[a][3]);
            *reinterpret_cast<float4*>(&Wt[(e0 + a) * 132 + c0]) = o;
        }
        __syncthreads();

        // ---- contraction: owner-computes, no atomics ----
        // 116 slots/edge: [0,48) out0a, [48,96) out0b, [96,106) out1a, [106,116) out1b(v: 3 comps)
        const int cend = ct + NC;
        for (int s = tid; s < TE * 116; s += NTHREADS) {
            int e = s / 116, r = s % 116;
            float* Ae = &Acc[e * 136];
            const float* We = &Wt[e * 132];
            if (r < 48) {                 // w1: c = u*48+v, feat s[u] -> out0a[v]
                int v = r;
                int u = (ct > v) ? (ct - v + 47) / 48 : 0;
                int c = u * 48 + v;
                float a = Ae[v];
                const float* se = &sF[e * 48];
                while (u < 48 && c < cend) { a += se[u] * We[c - ct]; ++u; c += 48; }
                Ae[v] = a;
            } else if (r < 96) {          // w4: c = 2884+u*48+v, feat dot[u] -> out0b[v]
                int v = r - 48;
                int rel = ct - OFF4_;
                int u = (rel > v) ? (rel - v + 47) / 48 : 0;
                int c = OFF4_ + u * 48 + v;
                float a = Ae[48 + v];
                const float* de = &dotF[e * 10];
                while (u < 10 && c < cend) { a += de[u] * We[c - ct]; ++u; c += 48; }
                Ae[48 + v] = a;
            } else if (r < 106) {         // w2: c = 2304+u*10+v, feat s[u] -> out1a[v]
                int v = r - 96;
                int rel = ct - OFF2_;
                int u = (rel > v) ? (rel - v + 9) / 10 : 0;
                int c = OFF2_ + u * 10 + v;
                float a = Ae[96 + v];
                const float* se = &sF[e * 48];
                while (u < 48 && c < cend) { a += se[u] * We[c - ct]; ++u; c += 10; }
                Ae[96 + v] = a;
            } else {                      // w3: c = 2784+u*10+v, feat vin[u][i] -> out1b[v][i]
                int v = r - 106;
                int rel = ct - OFF3_;
                int u = (rel > v) ? (rel - v + 9) / 10 : 0;
                int c = OFF3_ + u * 10 + v;
                float a0 = Ae[106 + v * 3 + 0];
                float a1 = Ae[106 + v * 3 + 1];
                float a2 = Ae[106 + v * 3 + 2];
                const float* ve = &vinF[e * 30];
                while (u < 10 && c < cend) {
                    float wv = We[c - ct];
                    a0 += ve[u * 3 + 0] * wv;
                    a1 += ve[u * 3 + 1] * wv;
                    a2 += ve[u * 3 + 2] * wv;
                    ++u; c += 10;
                }
                Ae[106 + v * 3 + 0] = a0;
                Ae[106 + v * 3 + 1] = a1;
                Ae[106 + v * 3 + 2] = a2;
            }
        }
        __syncthreads();
    }

    // ---- epilogue: combine with sh, scatter-add to src nodes ----
    for (int idx = tid; idx < TE * CH_; idx += NTHREADS) {
        int e = idx / CH_, k = idx % CH_;
        int ge = e_base + e;
        if (ge >= N_EDGES) continue;
        float sh0 = shS[e * 4];
        float val;
        if (k < NS_) {
            val = (Acc[e * 136 + k] * sh0 + Acc[e * 136 + 48 + k]) * NORM0_;
        } else {
            int kk = k - NS_;
            int v = kk / 3, i = kk % 3;
            val = (Acc[e * 136 + 96 + v] * shS[e * 4 + 1 + i] +
                   Acc[e * 136 + 106 + kk] * sh0) * NORM1_;
        }
        int src = edge_index[ge];
        atomicAdd(&g_sum[(size_t)src * CH_ + k], val);
        if (k == 0) atomicAdd(&g_cnt[src], 1.f);
    }
}

// ---------------- K3: node average + residual + stat sums ----------------
__device__ __forceinline__ float block_sum256(float v, float* red) {
#pragma unroll
    for (int off = 16; off > 0; off >>= 1)
        v += __shfl_down_sync(0xffffffffu, v, off);
    int w = threadIdx.x >> 5;
    if ((threadIdx.x & 31) == 0) red[w] = v;
    __syncthreads();
    float r = 0.f;
    if (threadIdx.x < 8) {
        r = red[threadIdx.x];
#pragma unroll
        for (int off = 4; off > 0; off >>= 1)
            r += __shfl_down_sync(0xffu, r, off);
    }
    __syncthreads();
    return r;  // valid in thread 0
}

__global__ void k3_combine(const float* __restrict__ node_attr) {
    __shared__ float red[8];
    int n = blockIdx.x * 256 + threadIdx.x;
    bool valid = n < N_NODES;
    float inv = 1.f;
    if (valid) inv = 1.f / fmaxf(g_cnt[n], 1.f);
    for (int k = 0; k < CH_; ++k) {
        float o = 0.f;
        if (valid) {
            o = g_sum[(size_t)n * CH_ + k] * inv + node_attr[(size_t)n * CH_ + k];
            g_node[(size_t)n * CH_ + k] = o;
        }
        if (k < NS_) {
            float s1 = block_sum256(o, red);
            if (threadIdx.x == 0) atomicAdd(&g_stats[k], s1);
            float s2 = block_sum256(o * o, red);
            if (threadIdx.x == 0) atomicAdd(&g_stats[48 + k], s2);
        } else {
            float s2 = block_sum256(o * o, red);
            if (threadIdx.x == 0) atomicAdd(&g_stats[96 + (k - NS_) / 3], s2);
        }
    }
}

// ---------------- K4: batch norm + write output ----------------
__global__ void k4_final(const float* __restrict__ bn_w,
                         const float* __restrict__ bn_b,
                         float* __restrict__ out) {
    int idx = blockIdx.x * 256 + threadIdx.x;
    if (idx >= N_NODES * CH_) return;
    int k = idx % CH_;
    float o = g_node[idx];
    float res;
    if (k < NS_) {
        float mean = g_stats[k] * (1.f / N_NODES);
        float var  = g_stats[48 + k] * (1.f / N_NODES) - mean * mean;
        res = (o - mean) * rsqrtf(var + EPS_) * __ldg(&bn_w[k]) + __ldg(&bn_b[k]);
    } else {
        int v = (k - NS_) / 3;
        float vn = g_stats[96 + v] * (1.f / (3.f * N_NODES));
        res = o * rsqrtf(vn + EPS_) * __ldg(&bn_w[NS_ + v]);
    }
    out[idx] = res;
}

// ---------------- launch ----------------
extern "C" void kernel_launch(void* const* d_in, const int* in_sizes, int n_in,
                              void* d_out, int out_size) {
    const float* node_attr  = (const float*)d_in[0];
    const int*   edge_index = (const int*)  d_in[1];
    const float* edge_attr  = (const float*)d_in[2];
    const float* edge_sh    = (const float*)d_in[3];
    const float* fc_w1      = (const float*)d_in[4];
    const float* fc_b1      = (const float*)d_in[5];
    const float* fc_w2      = (const float*)d_in[6];
    const float* fc_b2      = (const float*)d_in[7];
    const float* bn_w       = (const float*)d_in[8];
    const float* bn_b       = (const float*)d_in[9];
    float* out = (float*)d_out;

    cudaFuncSetAttribute(k1_hidden, cudaFuncAttributeMaxDynamicSharedMemorySize, SM1_BYTES);
    cudaFuncSetAttribute(k2_fused,  cudaFuncAttributeMaxDynamicSharedMemorySize, SM2_BYTES);

    const int gridE = (N_EDGES + TE - 1) / TE;

    k0_zero<<<512, 256>>>();
    k1_hidden<<<gridE, NTHREADS, SM1_BYTES>>>(edge_attr, fc_w1, fc_b1);
    k2_fused<<<gridE, NTHREADS, SM2_BYTES>>>(node_attr, edge_index, edge_sh, fc_w2, fc_b2);
    k3_combine<<<(N_NODES + 255) / 256, 256>>>(node_attr);
    k4_final<<<(N_NODES * CH_ + 255) / 256, 256>>>(bn_w, bn_b, out);
}